// round 4
// baseline (speedup 1.0000x reference)
#include <cuda_runtime.h>

// ---------------------------------------------------------------------------
// Problem constants
// ---------------------------------------------------------------------------
#define BB     16
#define CIN    1024
#define HW     1024      // 32*32
#define CK     256
#define CV     512
#define MTOT   768       // stacked key(256) + value(512) output channels
#define KTOT   9216      // CIN * 9

// ---------------------------------------------------------------------------
// Scratch (device globals; no allocation allowed)
// ---------------------------------------------------------------------------
__device__ float g_wT_t[KTOT * MTOT];          // temp-branch weights, [k][co]
__device__ float g_wT_s[KTOT * MTOT];          // search-branch weights
__device__ float g_mk[BB * CK * HW];           // m_key   [b][c][pix]
__device__ float g_qk[BB * CK * HW];           // q_key
__device__ float g_mv[BB * CV * HW];           // m_value
__device__ float g_S [BB * HW * HW];           // scores -> exp(scores)
__device__ float g_rsum[BB * HW];              // 1 / column sum

// ---------------------------------------------------------------------------
// Weight reshuffle: wT[(r*1024+ci)*768 + co] = w[co][ci][r]
// ---------------------------------------------------------------------------
__global__ void transpose_w(const float* __restrict__ wk,
                            const float* __restrict__ wv,
                            int which)
{
    int idx = blockIdx.x * blockDim.x + threadIdx.x;
    if (idx >= KTOT * MTOT) return;
    int k  = idx / MTOT;
    int co = idx - k * MTOT;
    int ci = k & 1023;
    int r  = k >> 10;
    float v = (co < CK) ? wk[co * KTOT + ci * 9 + r]
                        : wv[(co - CK) * KTOT + ci * 9 + r];
    (which ? g_wT_s : g_wT_t)[idx] = v;
}

// ---------------------------------------------------------------------------
// Implicit-GEMM conv: C[768, 16384] = wT^T-style GEMM with on-the-fly im2col.
// BM=BN=128, BK=32, 256 threads, 8x8 micro-tile (4+64 split quads).
// which==0: temp   -> key=g_mk, val=g_mv
// which==1: search -> key=g_qk, val=d_out (+512 chan offset)
// ---------------------------------------------------------------------------
__global__ __launch_bounds__(256, 2)
void conv_gemm(const float* __restrict__ src,
               const float* __restrict__ bias_k,
               const float* __restrict__ bias_v,
               float* __restrict__ out,     // only used for which==1 value path
               int which)
{
    __shared__ float As[32][128];
    __shared__ float Bs[32][128];

    const float* __restrict__ wT = which ? g_wT_s : g_wT_t;

    int tid = threadIdx.x;
    int tx  = tid & 15;          // n direction (16)
    int ty  = tid >> 4;          // m direction (16)
    int n0  = blockIdx.x * 128;  // pixel index over B*HW
    int co0 = blockIdx.y * 128;  // output channel
    int b   = n0 >> 10;
    int pix0 = n0 & 1023;
    const float* srcb = src + (size_t)b * (CIN * HW);

    int lrow = tid >> 5;          // 0..7
    int lcol = (tid & 31) * 4;    // 0..124

    // hoist pixel coords for B loads (independent of kt)
    int py[4], px[4];
#pragma unroll
    for (int t = 0; t < 4; ++t) {
        int pix = pix0 + lcol + t;
        py[t] = pix >> 5;
        px[t] = pix & 31;
    }

    float acc[8][8];
#pragma unroll
    for (int i = 0; i < 8; ++i)
#pragma unroll
        for (int j = 0; j < 8; ++j) acc[i][j] = 0.f;

    for (int kt = 0; kt < 288; ++kt) {
        int r   = kt >> 5;            // filter tap 0..8
        int ci0 = (kt & 31) << 5;     // input-channel base
        int dy  = r / 3 - 1;
        int dx  = r % 3 - 1;

        // --- load A tile (coalesced float4) ---
        const float* wrow = wT + (size_t)(kt * 32) * MTOT + co0;
#pragma unroll
        for (int p = 0; p < 4; ++p) {
            int kk = p * 8 + lrow;
            float4 v = *reinterpret_cast<const float4*>(&wrow[(size_t)kk * MTOT + lcol]);
            *reinterpret_cast<float4*>(&As[kk][lcol]) = v;
        }
        // --- load B tile (im2col gather) ---
#pragma unroll
        for (int p = 0; p < 4; ++p) {
            int kk = p * 8 + lrow;
            const float* srcc = srcb + (size_t)(ci0 + kk) * HW;
            float4 v;
            float tmp[4];
#pragma unroll
            for (int t = 0; t < 4; ++t) {
                int iy = py[t] + dy;
                int ix = px[t] + dx;
                float vv = 0.f;
                if ((unsigned)iy < 32u && (unsigned)ix < 32u)
                    vv = srcc[iy * 32 + ix];
                tmp[t] = vv;
            }
            v.x = tmp[0]; v.y = tmp[1]; v.z = tmp[2]; v.w = tmp[3];
            *reinterpret_cast<float4*>(&Bs[kk][lcol]) = v;
        }
        __syncthreads();

#pragma unroll 8
        for (int kk = 0; kk < 32; ++kk) {
            float4 a0 = *reinterpret_cast<const float4*>(&As[kk][ty * 4]);
            float4 a1 = *reinterpret_cast<const float4*>(&As[kk][ty * 4 + 64]);
            float4 b0 = *reinterpret_cast<const float4*>(&Bs[kk][tx * 4]);
            float4 b1 = *reinterpret_cast<const float4*>(&Bs[kk][tx * 4 + 64]);
            float a[8] = {a0.x, a0.y, a0.z, a0.w, a1.x, a1.y, a1.z, a1.w};
            float bv[8] = {b0.x, b0.y, b0.z, b0.w, b1.x, b1.y, b1.z, b1.w};
#pragma unroll
            for (int i = 0; i < 8; ++i)
#pragma unroll
                for (int j = 0; j < 8; ++j)
                    acc[i][j] += a[i] * bv[j];
        }
        __syncthreads();
    }

    // --- epilogue ---
    bool is_key = (co0 < CK);   // 128-row tiles never straddle the 256 boundary
#pragma unroll
    for (int i = 0; i < 8; ++i) {
        int row = ty * 4 + (i & 3) + ((i >> 2) << 6);
        int co  = co0 + row;
        float bias;
        float* dst;
        if (is_key) {
            bias = bias_k[co];
            dst  = (which ? g_qk : g_mk) + (size_t)b * (CK * HW) + (size_t)co * HW + pix0;
        } else {
            int cv = co - CK;
            bias = bias_v[cv];
            if (which) // q_value straight into output (channels 512..1023)
                dst = out + (size_t)b * (2 * CV * HW) + (size_t)(CV + cv) * HW + pix0;
            else
                dst = g_mv + (size_t)b * (CV * HW) + (size_t)cv * HW + pix0;
        }
#pragma unroll
        for (int jq = 0; jq < 2; ++jq) {
            int col = tx * 4 + jq * 64;
            float4 o;
            o.x = acc[i][jq * 4 + 0] + bias;
            o.y = acc[i][jq * 4 + 1] + bias;
            o.z = acc[i][jq * 4 + 2] + bias;
            o.w = acc[i][jq * 4 + 3] + bias;
            *reinterpret_cast<float4*>(&dst[col]) = o;
        }
    }
}

// ---------------------------------------------------------------------------
// Scores: S[b][m][q] = (1/16) * sum_c mk[b][c][m] * qk[b][c][q]
// ---------------------------------------------------------------------------
__global__ __launch_bounds__(256, 2)
void scores_gemm()
{
    __shared__ float As[32][128];
    __shared__ float Bs[32][128];
    int tid = threadIdx.x, tx = tid & 15, ty = tid >> 4;
    int b  = blockIdx.z;
    int m0 = blockIdx.y * 128;
    int q0 = blockIdx.x * 128;
    const float* mk = g_mk + (size_t)b * (CK * HW);
    const float* qk = g_qk + (size_t)b * (CK * HW);

    int lrow = tid >> 5;
    int lcol = (tid & 31) * 4;

    float acc[8][8];
#pragma unroll
    for (int i = 0; i < 8; ++i)
#pragma unroll
        for (int j = 0; j < 8; ++j) acc[i][j] = 0.f;

    for (int k0 = 0; k0 < CK; k0 += 32) {
#pragma unroll
        for (int p = 0; p < 4; ++p) {
            int kk = p * 8 + lrow;
            *reinterpret_cast<float4*>(&As[kk][lcol]) =
                *reinterpret_cast<const float4*>(&mk[(size_t)(k0 + kk) * HW + m0 + lcol]);
            *reinterpret_cast<float4*>(&Bs[kk][lcol]) =
                *reinterpret_cast<const float4*>(&qk[(size_t)(k0 + kk) * HW + q0 + lcol]);
        }
        __syncthreads();
#pragma unroll 8
        for (int kk = 0; kk < 32; ++kk) {
            float4 a0 = *reinterpret_cast<const float4*>(&As[kk][ty * 4]);
            float4 a1 = *reinterpret_cast<const float4*>(&As[kk][ty * 4 + 64]);
            float4 b0 = *reinterpret_cast<const float4*>(&Bs[kk][tx * 4]);
            float4 b1 = *reinterpret_cast<const float4*>(&Bs[kk][tx * 4 + 64]);
            float a[8] = {a0.x, a0.y, a0.z, a0.w, a1.x, a1.y, a1.z, a1.w};
            float bv[8] = {b0.x, b0.y, b0.z, b0.w, b1.x, b1.y, b1.z, b1.w};
#pragma unroll
            for (int i = 0; i < 8; ++i)
#pragma unroll
                for (int j = 0; j < 8; ++j)
                    acc[i][j] += a[i] * bv[j];
        }
        __syncthreads();
    }

    const float scale = 0.0625f;  // 1/sqrt(256)
#pragma unroll
    for (int i = 0; i < 8; ++i) {
        int m = m0 + ty * 4 + (i & 3) + ((i >> 2) << 6);
        float* srow = g_S + (size_t)b * (HW * HW) + (size_t)m * HW + q0;
#pragma unroll
        for (int jq = 0; jq < 2; ++jq) {
            int col = tx * 4 + jq * 64;
            float4 o;
            o.x = acc[i][jq * 4 + 0] * scale;
            o.y = acc[i][jq * 4 + 1] * scale;
            o.z = acc[i][jq * 4 + 2] * scale;
            o.w = acc[i][jq * 4 + 3] * scale;
            *reinterpret_cast<float4*>(&srow[col]) = o;
        }
    }
}

// ---------------------------------------------------------------------------
// Column softmax over m (axis=1): S <- exp(S - colmax); g_rsum = 1/colsum
// block (32,8): 32 q-columns per block, 8-row strip-mined reduction.
// ---------------------------------------------------------------------------
__global__ void softmax_col()
{
    __shared__ float red[8][32];
    int tx = threadIdx.x, ty = threadIdx.y;
    int b = blockIdx.y;
    int q = blockIdx.x * 32 + tx;
    float* col = g_S + (size_t)b * (HW * HW) + q;

    float mx = -3.402823e38f;
    for (int m = ty; m < HW; m += 8)
        mx = fmaxf(mx, col[(size_t)m * HW]);
    red[ty][tx] = mx;
    __syncthreads();
    if (ty == 0) {
        float v = red[0][tx];
#pragma unroll
        for (int r = 1; r < 8; ++r) v = fmaxf(v, red[r][tx]);
        red[0][tx] = v;
    }
    __syncthreads();
    mx = red[0][tx];
    __syncthreads();

    float s = 0.f;
    for (int m = ty; m < HW; m += 8) {
        float e = __expf(col[(size_t)m * HW] - mx);
        col[(size_t)m * HW] = e;
        s += e;
    }
    red[ty][tx] = s;
    __syncthreads();
    if (ty == 0) {
        float v = red[0][tx];
#pragma unroll
        for (int r = 1; r < 8; ++r) v += red[r][tx];
        g_rsum[b * HW + q] = 1.0f / v;
    }
}

// ---------------------------------------------------------------------------
// Output: out[b][c][q] = (sum_m mv[b][c][m] * E[b][m][q]) * rsum[b][q]
// A is row-major [c][m] -> transposed smem load with +1 pad (scalar a-reads).
// ---------------------------------------------------------------------------
__global__ __launch_bounds__(256, 2)
void out_gemm(float* __restrict__ out)
{
    __shared__ float As[32][129];
    __shared__ float Bs[32][128];
    int tid = threadIdx.x, tx = tid & 15, ty = tid >> 4;
    int b  = blockIdx.z;
    int c0 = blockIdx.y * 128;
    int q0 = blockIdx.x * 128;
    const float* mv = g_mv + (size_t)b * (CV * HW);
    const float* E  = g_S  + (size_t)b * (HW * HW);

    float acc[8][8];
#pragma unroll
    for (int i = 0; i < 8; ++i)
#pragma unroll
        for (int j = 0; j < 8; ++j) acc[i][j] = 0.f;

    for (int k0 = 0; k0 < HW; k0 += 32) {
        // transposed A load: As[kk][mm] = mv[c0+mm][k0+kk]
#pragma unroll
        for (int p = 0; p < 4; ++p) {
            int mm = p * 32 + (tid >> 3);
            int k4 = (tid & 7) * 4;
            float4 v = *reinterpret_cast<const float4*>(&mv[(size_t)(c0 + mm) * HW + k0 + k4]);
            As[k4 + 0][mm] = v.x;
            As[k4 + 1][mm] = v.y;
            As[k4 + 2][mm] = v.z;
            As[k4 + 3][mm] = v.w;
        }
#pragma unroll
        for (int p = 0; p < 4; ++p) {
            int kk = p * 8 + (tid >> 5);
            int nn = (tid & 31) * 4;
            *reinterpret_cast<float4*>(&Bs[kk][nn]) =
                *reinterpret_cast<const float4*>(&E[(size_t)(k0 + kk) * HW + q0 + nn]);
        }
        __syncthreads();
#pragma unroll 8
        for (int kk = 0; kk < 32; ++kk) {
            float a[8];
#pragma unroll
            for (int i = 0; i < 8; ++i)
                a[i] = As[kk][ty * 4 + (i & 3) + ((i >> 2) << 6)];
            float4 b0 = *reinterpret_cast<const float4*>(&Bs[kk][tx * 4]);
            float4 b1 = *reinterpret_cast<const float4*>(&Bs[kk][tx * 4 + 64]);
            float bv[8] = {b0.x, b0.y, b0.z, b0.w, b1.x, b1.y, b1.z, b1.w};
#pragma unroll
            for (int i = 0; i < 8; ++i)
#pragma unroll
                for (int j = 0; j < 8; ++j)
                    acc[i][j] += a[i] * bv[j];
        }
        __syncthreads();
    }

    const float* rs = g_rsum + b * HW + q0;
    float4 r0 = *reinterpret_cast<const float4*>(&rs[tx * 4]);
    float4 r1 = *reinterpret_cast<const float4*>(&rs[tx * 4 + 64]);
    float rv[8] = {r0.x, r0.y, r0.z, r0.w, r1.x, r1.y, r1.z, r1.w};
#pragma unroll
    for (int i = 0; i < 8; ++i) {
        int c = c0 + ty * 4 + (i & 3) + ((i >> 2) << 6);
        float* drow = out + (size_t)b * (2 * CV * HW) + (size_t)c * HW + q0;
#pragma unroll
        for (int jq = 0; jq < 2; ++jq) {
            int col = tx * 4 + jq * 64;
            float4 o;
            o.x = acc[i][jq * 4 + 0] * rv[jq * 4 + 0];
            o.y = acc[i][jq * 4 + 1] * rv[jq * 4 + 1];
            o.z = acc[i][jq * 4 + 2] * rv[jq * 4 + 2];
            o.w = acc[i][jq * 4 + 3] * rv[jq * 4 + 3];
            *reinterpret_cast<float4*>(&drow[col]) = o;
        }
    }
}

// ---------------------------------------------------------------------------
// Launch
// ---------------------------------------------------------------------------
extern "C" void kernel_launch(void* const* d_in, const int* in_sizes, int n_in,
                              void* d_out, int out_size)
{
    const float* src_t = (const float*)d_in[0];
    const float* src_s = (const float*)d_in[1];
    const float* wk_m  = (const float*)d_in[2];
    const float* bk_m  = (const float*)d_in[3];
    const float* wv_m  = (const float*)d_in[4];
    const float* bv_m  = (const float*)d_in[5];
    const float* wk_q  = (const float*)d_in[6];
    const float* bk_q  = (const float*)d_in[7];
    const float* wv_q  = (const float*)d_in[8];
    const float* bv_q  = (const float*)d_in[9];
    float* out = (float*)d_out;

    // 1. weight reshuffle (both branches)
    {
        int n = KTOT * MTOT;
        int blk = (n + 255) / 256;
        transpose_w<<<blk, 256>>>(wk_m, wv_m, 0);
        transpose_w<<<blk, 256>>>(wk_q, wv_q, 1);
    }
    // 2. convs (implicit GEMM). grid: 16384/128 pixel-tiles x 768/128 chan-tiles
    {
        dim3 grid(128, 6);
        conv_gemm<<<grid, 256>>>(src_t, bk_m, bv_m, out, 0);
        conv_gemm<<<grid, 256>>>(src_s, bk_q, bv_q, out, 1);
    }
    // 3. attention scores
    {
        dim3 grid(8, 8, BB);
        scores_gemm<<<grid, 256>>>();
    }
    // 4. column softmax (over memory axis)
    {
        dim3 grid(32, BB);
        dim3 blk(32, 8);
        softmax_col<<<grid, blk>>>();
    }
    // 5. weighted memory readout -> out channels [0, 512)
    {
        dim3 grid(8, 4, BB);
        out_gemm<<<grid, 256>>>(out);
    }
}